// round 5
// baseline (speedup 1.0000x reference)
#include <cuda_runtime.h>
#include <cuda_bf16.h>
#include <stdint.h>

// RoIAlign: feat (B=4, C=256, H=200, W=304) fp32, rois (N,5) fp32
// OUT=7, SCALE=0.25, sampling_ratio=1, aligned=False
// out: (N, C, 7, 7) fp32

#define B_ 4
#define C_ 256
#define H_ 200
#define W_ 304
#define OUT_ 7
#define BINS_PER_ROI (OUT_ * OUT_)      // 49
#define HW_ (H_ * W_)                   // 60800
#define CHW_ (C_ * HW_)                 // 15,564,800
#define SCALE_ 0.25f

#define CG_ 32                          // channels per gather block
#define NCG_ (C_ / CG_)                 // 8 channel groups
#define GATHER_THREADS 224              // 1568 elems / 7 per thread, exact
#define ELEMS_PER_THREAD 7

#define MAX_ROIS 8192
__device__ int    g_off[MAX_ROIS * BINS_PER_ROI];   // b*CHW + y0*W + x0
__device__ float4 g_w[MAX_ROIS * BINS_PER_ROI];     // bilinear weights * valid
__device__ int    g_order[MAX_ROIS];                // rois sorted by batch

// ---------------------------------------------------------------------------
// Phase 0: single-block counting sort of rois by batch index (4 buckets),
// reading batch ids straight from rois. Order within a bucket is irrelevant
// (each roi writes a disjoint output slice), so the shared-atomic scatter is
// deterministic-output-safe.
// ---------------------------------------------------------------------------
__global__ __launch_bounds__(256)
void roi_sort_kernel(const float* __restrict__ rois, int n_rois) {
    __shared__ int s_count[B_];
    __shared__ int s_base[B_];
    __shared__ int s_pos[B_];

    int tid = threadIdx.x;
    if (tid < B_) s_count[tid] = 0;
    __syncthreads();

    for (int n = tid; n < n_rois; n += blockDim.x)
        atomicAdd(&s_count[(int)rois[n * 5]], 1);
    __syncthreads();

    if (tid == 0) {
        int acc = 0;
        for (int b = 0; b < B_; b++) { s_base[b] = acc; acc += s_count[b]; s_pos[b] = 0; }
    }
    __syncthreads();

    for (int n = tid; n < n_rois; n += blockDim.x) {
        int b = (int)rois[n * 5];
        int pos = s_base[b] + atomicAdd(&s_pos[b], 1);
        g_order[pos] = n;
    }
}

// ---------------------------------------------------------------------------
// Phase 1: one thread per (roi, bin).
// ---------------------------------------------------------------------------
__global__ __launch_bounds__(256)
void roi_prep_kernel(const float* __restrict__ rois, int n_bins) {
    int i = blockIdx.x * blockDim.x + threadIdx.x;
    if (i >= n_bins) return;

    int n  = i / BINS_PER_ROI;
    int p  = i - n * BINS_PER_ROI;
    int ph = p / OUT_;
    int pw = p - ph * OUT_;

    const float* r = rois + n * 5;
    int   b   = (int)r[0];
    float sx1 = r[1] * SCALE_;
    float sy1 = r[2] * SCALE_;
    float sx2 = r[3] * SCALE_;
    float sy2 = r[4] * SCALE_;

    float rw = fmaxf(sx2 - sx1, 1.0f);   // aligned=False -> clamp to 1
    float rh = fmaxf(sy2 - sy1, 1.0f);
    float bin_w = rw * (1.0f / OUT_);
    float bin_h = rh * (1.0f / OUT_);

    // sampling_ratio = 1: single sample at bin center
    float x = sx1 + ((float)pw + 0.5f) * bin_w;
    float y = sy1 + ((float)ph + 0.5f) * bin_h;

    float valid = (y > -1.0f && y < (float)H_ && x > -1.0f && x < (float)W_)
                      ? 1.0f : 0.0f;

    y = fminf(fmaxf(y, 0.0f), (float)(H_ - 1));
    x = fminf(fmaxf(x, 0.0f), (float)(W_ - 1));

    int   y0 = (int)floorf(y);
    int   x0 = (int)floorf(x);
    float ly = y - (float)y0;
    float lx = x - (float)x0;

    // Edge re-parameterization: keep (y0+1, x0+1) taps in-bounds.
    if (y0 >= H_ - 1) { y0 = H_ - 2; ly = 1.0f; }
    if (x0 >= W_ - 1) { x0 = W_ - 2; lx = 1.0f; }

    float hy = 1.0f - ly;
    float hx = 1.0f - lx;

    g_off[i] = b * CHW_ + y0 * W_ + x0;
    g_w[i]   = make_float4(hy * hx * valid,
                           hy * lx * valid,
                           ly * hx * valid,
                           ly * lx * valid);
}

// ---------------------------------------------------------------------------
// Phase 2: one block = (batch-sorted roi slot, 32-channel group).
// 224 threads x 7 elements each = 1568 (exact, no bounds checks).
// All 28 feature loads per thread are issued before any consumption,
// raising per-thread MLP from 4 to 28 so load latency overlaps instead
// of serializing per element. Stores remain fully coalesced.
// ---------------------------------------------------------------------------
__global__ __launch_bounds__(GATHER_THREADS)
void roi_gather_kernel(const float* __restrict__ feat,
                       float* __restrict__ out) {
    __shared__ int    s_off[BINS_PER_ROI];
    __shared__ float4 s_w[BINS_PER_ROI];

    int slot = blockIdx.x >> 3;          // / NCG_ (8)
    int cg   = blockIdx.x & (NCG_ - 1);
    int n    = g_order[slot];
    int c0   = cg * CG_;

    int tid = threadIdx.x;
    if (tid < BINS_PER_ROI) {
        int bin = n * BINS_PER_ROI + tid;
        s_off[tid] = g_off[bin];
        s_w[tid]   = g_w[bin];
    }
    __syncthreads();

    float* out_base = out + (n * C_ + c0) * BINS_PER_ROI;

    float  f00[ELEMS_PER_THREAD], f01[ELEMS_PER_THREAD];
    float  f10[ELEMS_PER_THREAD], f11[ELEMS_PER_THREAD];
    float4 wv[ELEMS_PER_THREAD];

    // Phase A: issue all 28 independent loads.
    #pragma unroll
    for (int i = 0; i < ELEMS_PER_THREAD; i++) {
        int idx = tid + i * GATHER_THREADS;
        int c   = idx / BINS_PER_ROI;
        int p   = idx - c * BINS_PER_ROI;

        int off = s_off[p] + (c0 + c) * HW_;
        wv[i]   = s_w[p];

        const float* ptr = feat + off;
        f00[i] = __ldg(ptr);
        f01[i] = __ldg(ptr + 1);
        f10[i] = __ldg(ptr + W_);
        f11[i] = __ldg(ptr + W_ + 1);
    }

    // Phase B: blend and store (coalesced).
    #pragma unroll
    for (int i = 0; i < ELEMS_PER_THREAD; i++) {
        out_base[tid + i * GATHER_THREADS] =
            f00[i] * wv[i].x + f01[i] * wv[i].y +
            f10[i] * wv[i].z + f11[i] * wv[i].w;
    }
}

// ---------------------------------------------------------------------------
extern "C" void kernel_launch(void* const* d_in, const int* in_sizes, int n_in,
                              void* d_out, int out_size) {
    const float* feat = (const float*)d_in[0];
    const float* rois = (const float*)d_in[1];
    float* out = (float*)d_out;

    int N = in_sizes[1] / 5;
    int n_bins = N * BINS_PER_ROI;

    roi_sort_kernel<<<1, 256>>>(rois, N);
    roi_prep_kernel<<<(n_bins + 255) / 256, 256>>>(rois, n_bins);
    roi_gather_kernel<<<N * NCG_, GATHER_THREADS>>>(feat, out);
}